// round 2
// baseline (speedup 1.0000x reference)
#include <cuda_runtime.h>
#include <cuda_bf16.h>

// Problem: B=8, SEQ=4096, DIM=64.
// out = scale * Q_r @ (K_r^T @ V_r)   (associativity; no softmax in reference)
// scale = 1/sqrt(64) = 0.125
//
// Inputs (metadata order): q, k, v, freq_q, freq_k, freq_v
//   q/k/v: (8, 4096, 64) fp32 ; freq_*: (4096, 32, 2) fp32
// Output: (8, 4096, 64) fp32

#define BATCH   8
#define SEQ     4096
#define DIM     64
#define NCHUNK  64
#define CHUNK   (SEQ / NCHUNK)   // 64 rows per k1 block
#define TROWS   16               // rows per shared tile in k1

// Scratch (device globals — no allocation allowed)
__device__ float g_partials[NCHUNK * BATCH * DIM * DIM];  // 8 MB
__device__ float g_M[BATCH * DIM * DIM];                  // 128 KB

// ---- packed f32x2 helpers (sm_10x FFMA2 path) ------------------------------
__device__ __forceinline__ unsigned long long pk2(float x, float y) {
    unsigned long long r;
    asm("mov.b64 %0, {%1,%2};" : "=l"(r) : "f"(x), "f"(y));
    return r;
}
__device__ __forceinline__ void fma2(unsigned long long& d,
                                     unsigned long long a,
                                     unsigned long long b) {
    asm("fma.rn.f32x2 %0, %1, %2, %0;" : "+l"(d) : "l"(a), "l"(b));
}
__device__ __forceinline__ float2 up2(unsigned long long v) {
    float2 r;
    asm("mov.b64 {%0,%1}, %2;" : "=f"(r.x), "=f"(r.y) : "l"(v));
    return r;
}

// ---------------------------------------------------------------------------
// Kernel 1: per (chunk, batch) block: partial M = sum_rows rope(k) ⊗ rope(v)
// 256 threads; 16x16 thread grid, each thread owns a 4x4 tile of M (as 4x2
// packed f32x2 accumulators).
// ---------------------------------------------------------------------------
__global__ __launch_bounds__(256) void kv_outer_kernel(
    const float* __restrict__ K, const float* __restrict__ V,
    const float* __restrict__ FK, const float* __restrict__ FV)
{
    const int b = blockIdx.y;
    const int c = blockIdx.x;
    const int t = threadIdx.x;

    __shared__ float sk[TROWS][DIM];
    __shared__ float sv[TROWS][DIM];

    unsigned long long acc[4][2];
#pragma unroll
    for (int i = 0; i < 4; i++) { acc[i][0] = 0ULL; acc[i][1] = 0ULL; }

    const int ti = t >> 4;            // 0..15
    const int tj = t & 15;            // 0..15
    const int i0 = ti * 4;
    const int j0 = tj * 4;

    // load mapping: 16 rows x 16 threads-per-row, each loads a float4 (2 pairs)
    const int lr = t >> 4;            // row within tile
    const int lp = t & 15;            // float4 slot (cols 4*lp..4*lp+3)

    const size_t base = ((size_t)b * SEQ) * DIM;
    const int row0 = c * CHUNK;

    for (int tile = 0; tile < CHUNK / TROWS; tile++) {
        const int row = row0 + tile * TROWS + lr;
        const float4 kq = *(const float4*)&K [base + (size_t)row * DIM + 4 * lp];
        const float4 vq = *(const float4*)&V [base + (size_t)row * DIM + 4 * lp];
        const float4 fk = *(const float4*)&FK[(size_t)row * DIM + 4 * lp];
        const float4 fv = *(const float4*)&FV[(size_t)row * DIM + 4 * lp];

        float4 kr, vr;
        kr.x = kq.x * fk.x - kq.y * fk.y;  kr.y = kq.x * fk.y + kq.y * fk.x;
        kr.z = kq.z * fk.z - kq.w * fk.w;  kr.w = kq.z * fk.w + kq.w * fk.z;
        vr.x = vq.x * fv.x - vq.y * fv.y;  vr.y = vq.x * fv.y + vq.y * fv.x;
        vr.z = vq.z * fv.z - vq.w * fv.w;  vr.w = vq.z * fv.w + vq.w * fv.z;

        __syncthreads();                    // WAR: previous tile fully consumed
        *(float4*)&sk[lr][4 * lp] = kr;
        *(float4*)&sv[lr][4 * lp] = vr;
        __syncthreads();

#pragma unroll
        for (int r = 0; r < TROWS; r++) {
            const float4 kk = *(const float4*)&sk[r][i0];
            const unsigned long long v01 = *(const unsigned long long*)&sv[r][j0];
            const unsigned long long v23 = *(const unsigned long long*)&sv[r][j0 + 2];
            const unsigned long long k0 = pk2(kk.x, kk.x);
            const unsigned long long k1 = pk2(kk.y, kk.y);
            const unsigned long long k2 = pk2(kk.z, kk.z);
            const unsigned long long k3 = pk2(kk.w, kk.w);
            fma2(acc[0][0], k0, v01);  fma2(acc[0][1], k0, v23);
            fma2(acc[1][0], k1, v01);  fma2(acc[1][1], k1, v23);
            fma2(acc[2][0], k2, v01);  fma2(acc[2][1], k2, v23);
            fma2(acc[3][0], k3, v01);  fma2(acc[3][1], k3, v23);
        }
    }

    float* P = &g_partials[((size_t)c * BATCH + b) * (DIM * DIM)];
#pragma unroll
    for (int i = 0; i < 4; i++) {
        const float2 a = up2(acc[i][0]);
        const float2 c2 = up2(acc[i][1]);
        *(float4*)&P[(i0 + i) * DIM + j0] = make_float4(a.x, a.y, c2.x, c2.y);
    }
}

// ---------------------------------------------------------------------------
// Kernel 2: reduce NCHUNK partials -> g_M   (8192 float4 elements)
// ---------------------------------------------------------------------------
__global__ __launch_bounds__(256) void reduce_kernel()
{
    const int idx = blockIdx.x * 256 + threadIdx.x;   // 0..8191 (float4 units)
    const float4* P = (const float4*)g_partials;
    float4 s0 = make_float4(0.f, 0.f, 0.f, 0.f);
    float4 s1 = make_float4(0.f, 0.f, 0.f, 0.f);
#pragma unroll
    for (int c = 0; c < NCHUNK; c += 2) {
        const float4 a = P[(size_t)c * 8192 + idx];
        const float4 b = P[(size_t)(c + 1) * 8192 + idx];
        s0.x += a.x; s0.y += a.y; s0.z += a.z; s0.w += a.w;
        s1.x += b.x; s1.y += b.y; s1.z += b.z; s1.w += b.w;
    }
    ((float4*)g_M)[idx] = make_float4(s0.x + s1.x, s0.y + s1.y,
                                      s0.z + s1.z, s0.w + s1.w);
}

// ---------------------------------------------------------------------------
// Kernel 3: out[b,row,:] = scale * rope(Q[b,row,:]) @ M[b]
// 256 threads per block, 64 rows per block. Thread (row rr = t>>2, quarter
// lp = t&3) ropes 16 q values and computes 16 output columns with 8 packed
// f32x2 accumulators (independent chains -> good ILP).
// ---------------------------------------------------------------------------
#define QSTRIDE 68   // padded shared stride: (4r+d)%32 distinct per warp, 16B-aligned rows

__global__ __launch_bounds__(256) void qm_kernel(
    const float* __restrict__ Q, const float* __restrict__ FQ,
    float* __restrict__ OUT)
{
    const int b = blockIdx.y;
    const int rchunk = blockIdx.x;          // 64 rows each
    const int t = threadIdx.x;

    __shared__ float sM[DIM * DIM];         // 16 KB
    __shared__ float sq[DIM * QSTRIDE];     // 17 KB (padded)

    // load M[b]
    {
        const float4* Ms = (const float4*)&g_M[(size_t)b * DIM * DIM];
        float4* Md = (float4*)sM;
#pragma unroll
        for (int i = 0; i < 4; i++) Md[t + 256 * i] = Ms[t + 256 * i];
    }

    const int rr = t >> 2;                  // 0..63 row within block
    const int lp = t & 3;                   // quarter of the row
    const int j0 = lp * 16;
    const size_t base = ((size_t)b * SEQ) * DIM;
    const int row = rchunk * 64 + rr;

    // rope 16 q values into padded shared
    {
        const float4* qs = (const float4*)&Q [base + (size_t)row * DIM + j0];
        const float4* fs = (const float4*)&FQ[(size_t)row * DIM + j0];
        float* dst = &sq[rr * QSTRIDE + j0];
#pragma unroll
        for (int u = 0; u < 4; u++) {
            const float4 qv = qs[u];
            const float4 fv = fs[u];
            float4 o;
            o.x = qv.x * fv.x - qv.y * fv.y;  o.y = qv.x * fv.y + qv.y * fv.x;
            o.z = qv.z * fv.z - qv.w * fv.w;  o.w = qv.z * fv.w + qv.w * fv.z;
            *(float4*)&dst[4 * u] = o;
        }
    }
    __syncthreads();

    unsigned long long acc[8];
#pragma unroll
    for (int u = 0; u < 8; u++) acc[u] = 0ULL;

    const float* qrow = &sq[rr * QSTRIDE];
#pragma unroll 8
    for (int d = 0; d < DIM; d++) {
        const unsigned long long q2 = pk2(qrow[d], qrow[d]);
        const unsigned long long* mrow = (const unsigned long long*)&sM[d * DIM + j0];
#pragma unroll
        for (int u = 0; u < 8; u++) fma2(acc[u], q2, mrow[u]);
    }

    const float scale = 0.125f;   // 1/sqrt(64)
    float* o = &OUT[base + (size_t)row * DIM + j0];
#pragma unroll
    for (int u = 0; u < 4; u++) {
        const float2 a = up2(acc[2 * u]);
        const float2 c2 = up2(acc[2 * u + 1]);
        *(float4*)&o[4 * u] = make_float4(a.x * scale, a.y * scale,
                                          c2.x * scale, c2.y * scale);
    }
}

// ---------------------------------------------------------------------------
extern "C" void kernel_launch(void* const* d_in, const int* in_sizes, int n_in,
                              void* d_out, int out_size)
{
    const float* q  = (const float*)d_in[0];
    const float* k  = (const float*)d_in[1];
    const float* v  = (const float*)d_in[2];
    const float* fq = (const float*)d_in[3];
    const float* fk = (const float*)d_in[4];
    const float* fv = (const float*)d_in[5];
    float* out = (float*)d_out;

    kv_outer_kernel<<<dim3(NCHUNK, BATCH), 256>>>(k, v, fk, fv);
    reduce_kernel<<<(BATCH * DIM * DIM / 4) / 256, 256>>>();
    qm_kernel<<<dim3(SEQ / 64, BATCH), 256>>>(q, fq, out);
}

// round 3
// speedup vs baseline: 1.4268x; 1.4268x over previous
#include <cuda_runtime.h>
#include <cuda_bf16.h>

// B=8, SEQ=4096, DIM=64.
// out = scale * rope(Q) @ (rope(K)^T @ rope(V))   (associativity; no softmax)
// scale = 1/sqrt(64) = 0.125
// Inputs: q,k,v (8,4096,64) fp32 ; freq_q/k/v (4096,32,2) fp32. Output fp32.

#define BATCH   8
#define SEQ     4096
#define DIM     64
#define NCHUNK  128
#define CHUNK   (SEQ / NCHUNK)   // 32 rows per k1 block

// Scratch (device globals — no allocation allowed)
__device__ float g_partials[NCHUNK * BATCH * DIM * DIM];  // 16 MB
__device__ float g_M[BATCH * DIM * DIM];                  // 128 KB

// ---- packed f32x2 helpers (sm_10x FFMA2 path) ------------------------------
__device__ __forceinline__ unsigned long long pk2(float x, float y) {
    unsigned long long r;
    asm("mov.b64 %0, {%1,%2};" : "=l"(r) : "f"(x), "f"(y));
    return r;
}
__device__ __forceinline__ void fma2(unsigned long long& d,
                                     unsigned long long a,
                                     unsigned long long b) {
    asm("fma.rn.f32x2 %0, %1, %2, %0;" : "+l"(d) : "l"(a), "l"(b));
}
__device__ __forceinline__ float2 up2(unsigned long long v) {
    float2 r;
    asm("mov.b64 {%0,%1}, %2;" : "=f"(r.x), "=f"(r.y) : "l"(v));
    return r;
}
__device__ __forceinline__ float4 rope4(float4 x, float4 f) {
    float4 o;
    o.x = x.x * f.x - x.y * f.y;  o.y = x.x * f.y + x.y * f.x;
    o.z = x.z * f.z - x.w * f.w;  o.w = x.z * f.w + x.w * f.z;
    return o;
}

// ---------------------------------------------------------------------------
// Kernel 1: per (chunk, batch) block: partial M = sum_rows rope(k) ⊗ rope(v)
// 128 threads. Thread (ti = t&15, tj = t>>4) owns M rows 4ti..4ti+3,
// cols 8tj..8tj+7 as 4x4 packed f32x2 accumulators.
// Lane mapping ti = t&15 makes the sk LDS.128 cover all 32 banks (conflict-
// free); sv LDS.64 has 2 addresses/warp broadcast 16-way (conflict-free).
// ---------------------------------------------------------------------------
__global__ __launch_bounds__(128) void kv_outer_kernel(
    const float* __restrict__ K, const float* __restrict__ V,
    const float* __restrict__ FK, const float* __restrict__ FV)
{
    const int b = blockIdx.y;
    const int c = blockIdx.x;
    const int t = threadIdx.x;

    __shared__ float sk[CHUNK][DIM];   // 8 KB
    __shared__ float sv[CHUNK][DIM];   // 8 KB

    const float4* K4  = (const float4*)(K  + ((size_t)b * SEQ + c * CHUNK) * DIM);
    const float4* V4  = (const float4*)(V  + ((size_t)b * SEQ + c * CHUNK) * DIM);
    const float4* FK4 = (const float4*)(FK + (size_t)c * CHUNK * DIM);
    const float4* FV4 = (const float4*)(FV + (size_t)c * CHUNK * DIM);

    // stage + rope the 32x64 tile (512 float4 per tensor, 4 per thread)
#pragma unroll
    for (int u = 0; u < 4; u++) {
        const int f = t + 128 * u;
        const int row = f >> 4;
        const int c4 = f & 15;
        const float4 kr = rope4(K4[f], FK4[f]);
        const float4 vr = rope4(V4[f], FV4[f]);
        *(float4*)&sk[row][4 * c4] = kr;
        *(float4*)&sv[row][4 * c4] = vr;
    }
    __syncthreads();

    const int ti = t & 15;
    const int tj = t >> 4;
    const int i0 = 4 * ti;
    const int j0 = 8 * tj;

    unsigned long long acc[4][4];
#pragma unroll
    for (int i = 0; i < 4; i++)
#pragma unroll
        for (int u = 0; u < 4; u++) acc[i][u] = 0ULL;

#pragma unroll 8
    for (int r = 0; r < CHUNK; r++) {
        const float4 kk = *(const float4*)&sk[r][i0];
        const unsigned long long* vr = (const unsigned long long*)&sv[r][j0];
        const unsigned long long v0 = vr[0], v1 = vr[1], v2 = vr[2], v3 = vr[3];
        const unsigned long long k0 = pk2(kk.x, kk.x);
        const unsigned long long k1 = pk2(kk.y, kk.y);
        const unsigned long long k2 = pk2(kk.z, kk.z);
        const unsigned long long k3 = pk2(kk.w, kk.w);
        fma2(acc[0][0], k0, v0); fma2(acc[0][1], k0, v1);
        fma2(acc[0][2], k0, v2); fma2(acc[0][3], k0, v3);
        fma2(acc[1][0], k1, v0); fma2(acc[1][1], k1, v1);
        fma2(acc[1][2], k1, v2); fma2(acc[1][3], k1, v3);
        fma2(acc[2][0], k2, v0); fma2(acc[2][1], k2, v1);
        fma2(acc[2][2], k2, v2); fma2(acc[2][3], k2, v3);
        fma2(acc[3][0], k3, v0); fma2(acc[3][1], k3, v1);
        fma2(acc[3][2], k3, v2); fma2(acc[3][3], k3, v3);
    }

    float* P = &g_partials[((size_t)c * BATCH + b) * (DIM * DIM)];
#pragma unroll
    for (int i = 0; i < 4; i++) {
#pragma unroll
        for (int w = 0; w < 2; w++) {
            const float2 a = up2(acc[i][2 * w]);
            const float2 b2 = up2(acc[i][2 * w + 1]);
            *(float4*)&P[(i0 + i) * DIM + j0 + 4 * w] =
                make_float4(a.x, a.y, b2.x, b2.y);
        }
    }
}

// ---------------------------------------------------------------------------
// Kernel 2: reduce NCHUNK partials -> g_M  (8192 float4 outputs)
// ---------------------------------------------------------------------------
__global__ __launch_bounds__(256) void reduce_kernel()
{
    const int idx = blockIdx.x * 256 + threadIdx.x;   // float4 index, 0..8191
    const float4* P = (const float4*)g_partials;
    float4 s0 = make_float4(0.f, 0.f, 0.f, 0.f);
    float4 s1 = make_float4(0.f, 0.f, 0.f, 0.f);
    float4 s2 = make_float4(0.f, 0.f, 0.f, 0.f);
    float4 s3 = make_float4(0.f, 0.f, 0.f, 0.f);
#pragma unroll 4
    for (int c = 0; c < NCHUNK; c += 4) {
        const float4 a = P[(size_t)(c + 0) * 8192 + idx];
        const float4 b = P[(size_t)(c + 1) * 8192 + idx];
        const float4 d = P[(size_t)(c + 2) * 8192 + idx];
        const float4 e = P[(size_t)(c + 3) * 8192 + idx];
        s0.x += a.x; s0.y += a.y; s0.z += a.z; s0.w += a.w;
        s1.x += b.x; s1.y += b.y; s1.z += b.z; s1.w += b.w;
        s2.x += d.x; s2.y += d.y; s2.z += d.z; s2.w += d.w;
        s3.x += e.x; s3.y += e.y; s3.z += e.z; s3.w += e.w;
    }
    ((float4*)g_M)[idx] = make_float4(s0.x + s1.x + s2.x + s3.x,
                                      s0.y + s1.y + s2.y + s3.y,
                                      s0.z + s1.z + s2.z + s3.z,
                                      s0.w + s1.w + s2.w + s3.w);
}

// ---------------------------------------------------------------------------
// Kernel 3: out[b, r, :] = scale * rope(Q[b, r, :]) @ M[b]
// Same 4x8 register tiling as kernel 1. rope(Q) is staged TRANSPOSED in
// shared (sqT[d][row], stride 68: 16B-aligned rows, conflict-free LDS.128).
// Block = 64 q rows x 64 cols, 128 threads.
// ---------------------------------------------------------------------------
#define QPAD 68

__global__ __launch_bounds__(128) void qm_kernel(
    const float* __restrict__ Q, const float* __restrict__ FQ,
    float* __restrict__ OUT)
{
    const int b = blockIdx.y;
    const int rc = blockIdx.x;   // 64-row chunk
    const int t = threadIdx.x;

    __shared__ float sM[DIM * DIM];      // 16 KB
    __shared__ float sqT[DIM][QPAD];     // 17 KB, [d][row]

    // load M[b] (L2-resident after first wave)
    {
        const float4* Ms = (const float4*)&g_M[(size_t)b * DIM * DIM];
        float4* Md = (float4*)sM;
#pragma unroll
        for (int u = 0; u < 8; u++) Md[t + 128 * u] = Ms[t + 128 * u];
    }

    // stage rope(Q) transposed: 64x64 tile = 1024 float4, 8 per thread
    const size_t gbase = ((size_t)b * SEQ + (size_t)rc * 64) * DIM;
    {
        const float4* Q4 = (const float4*)(Q + gbase);
        const float4* F4 = (const float4*)(FQ + (size_t)rc * 64 * DIM);
#pragma unroll
        for (int u = 0; u < 8; u++) {
            const int f = t + 128 * u;
            const int row = f >> 4;
            const int d0 = 4 * (f & 15);
            const float4 o = rope4(Q4[f], F4[f]);
            sqT[d0][row]     = o.x;
            sqT[d0 + 1][row] = o.y;
            sqT[d0 + 2][row] = o.z;
            sqT[d0 + 3][row] = o.w;
        }
    }
    __syncthreads();

    const int ti = t & 15;
    const int tj = t >> 4;
    const int i0 = 4 * ti;    // q rows within chunk
    const int j0 = 8 * tj;    // output cols

    unsigned long long acc[4][4];
#pragma unroll
    for (int i = 0; i < 4; i++)
#pragma unroll
        for (int u = 0; u < 4; u++) acc[i][u] = 0ULL;

#pragma unroll 8
    for (int d = 0; d < DIM; d++) {
        const float4 qq = *(const float4*)&sqT[d][i0];
        const unsigned long long* mr = (const unsigned long long*)&sM[d * DIM + j0];
        const unsigned long long m0 = mr[0], m1 = mr[1], m2 = mr[2], m3 = mr[3];
        const unsigned long long q0 = pk2(qq.x, qq.x);
        const unsigned long long q1 = pk2(qq.y, qq.y);
        const unsigned long long q2 = pk2(qq.z, qq.z);
        const unsigned long long q3 = pk2(qq.w, qq.w);
        fma2(acc[0][0], q0, m0); fma2(acc[0][1], q0, m1);
        fma2(acc[0][2], q0, m2); fma2(acc[0][3], q0, m3);
        fma2(acc[1][0], q1, m0); fma2(acc[1][1], q1, m1);
        fma2(acc[1][2], q1, m2); fma2(acc[1][3], q1, m3);
        fma2(acc[2][0], q2, m0); fma2(acc[2][1], q2, m1);
        fma2(acc[2][2], q2, m2); fma2(acc[2][3], q2, m3);
        fma2(acc[3][0], q3, m0); fma2(acc[3][1], q3, m1);
        fma2(acc[3][2], q3, m2); fma2(acc[3][3], q3, m3);
    }

    const float scale = 0.125f;   // 1/sqrt(64)
    float* O = OUT + gbase;
#pragma unroll
    for (int i = 0; i < 4; i++) {
#pragma unroll
        for (int w = 0; w < 2; w++) {
            const float2 a = up2(acc[i][2 * w]);
            const float2 b2 = up2(acc[i][2 * w + 1]);
            *(float4*)&O[(size_t)(i0 + i) * DIM + j0 + 4 * w] =
                make_float4(a.x * scale, a.y * scale, b2.x * scale, b2.y * scale);
        }
    }
}

// ---------------------------------------------------------------------------
extern "C" void kernel_launch(void* const* d_in, const int* in_sizes, int n_in,
                              void* d_out, int out_size)
{
    const float* q  = (const float*)d_in[0];
    const float* k  = (const float*)d_in[1];
    const float* v  = (const float*)d_in[2];
    const float* fq = (const float*)d_in[3];
    const float* fk = (const float*)d_in[4];
    const float* fv = (const float*)d_in[5];
    float* out = (float*)d_out;

    kv_outer_kernel<<<dim3(NCHUNK, BATCH), 128>>>(k, v, fk, fv);
    reduce_kernel<<<(BATCH * DIM * DIM / 4) / 256, 256>>>();
    qm_kernel<<<dim3(SEQ / 64, BATCH), 128>>>(q, fq, out);
}